// round 1
// baseline (speedup 1.0000x reference)
#include <cuda_runtime.h>
#include <stdint.h>

// Problem constants (fixed by the dataset problem).
#define HH 112
#define WW 112
#define MAXB 4   // scratch sized for up to 4 batches; actual B derived at launch

// Per-pixel winner key: high 32 bits = order-preserving encoded depth,
// low 32 bits = ~triangle_index (so equal depth -> smaller index wins).
// 0 means "uncovered" (any finite encoded depth is > 0 in the high word).
__device__ unsigned long long g_keys[MAXB * HH * WW];

__device__ __forceinline__ unsigned int fenc(float f) {
    unsigned int u = __float_as_uint(f);
    return (u & 0x80000000u) ? ~u : (u | 0x80000000u);
}

__global__ void init_keys(int n) {
    int i = blockIdx.x * blockDim.x + threadIdx.x;
    if (i < n) g_keys[i] = 0ull;
}

__global__ void raster_kernel(const float* __restrict__ vertices,
                              const int*   __restrict__ triangles,
                              int B, int ntri, int nver) {
    int idx = blockIdx.x * blockDim.x + threadIdx.x;
    if (idx >= B * ntri) return;
    int b = idx / ntri;
    int t = idx - b * ntri;

    int i0 = triangles[t];
    int i1 = triangles[ntri + t];
    int i2 = triangles[2 * ntri + t];

    const float* V = vertices + (size_t)b * 3 * nver;
    float x0 = V[i0],            x1 = V[i1],            x2 = V[i2];
    float y0 = V[nver + i0],     y1 = V[nver + i1],     y2 = V[nver + i2];
    float z0 = V[2 * nver + i0], z1 = V[2 * nver + i1], z2 = V[2 * nver + i2];

    float depth = ((z0 + z1) + z2) / 3.0f;

    float xmin = fminf(fminf(x0, x1), x2);
    float xmax = fmaxf(fmaxf(x0, x1), x2);
    float ymin = fminf(fminf(y0, y1), y2);
    float ymax = fmaxf(fmaxf(y0, y1), y2);

    // Match reference: max(ceil(min),0), min(floor(max), W-1) in float then cast.
    int umin = (int)fmaxf(ceilf(xmin), 0.0f);
    int umax = (int)fminf(floorf(xmax), (float)(WW - 1));
    int vmin = (int)fmaxf(ceilf(ymin), 0.0f);
    int vmax = (int)fminf(floorf(ymax), (float)(HH - 1));
    if (umin > umax || vmin > vmax) return;

    unsigned long long key =
        ((unsigned long long)fenc(depth) << 32) | (unsigned int)(~(unsigned int)t);

    unsigned long long* base = g_keys + (size_t)b * HH * WW;
    for (int v = vmin; v <= vmax; ++v) {
        unsigned long long* row = base + (size_t)v * WW;
        for (int u = umin; u <= umax; ++u) {
            atomicMax(&row[u], key);
        }
    }
}

__global__ void resolve_kernel(const float* __restrict__ colors,
                               const int*   __restrict__ triangles,
                               float* __restrict__ out,
                               int B, int ntri, int nver) {
    int p = blockIdx.x * blockDim.x + threadIdx.x;
    int npix = B * HH * WW;
    if (p >= npix) return;
    int b = p / (HH * WW);
    int pix = p - b * (HH * WW);

    unsigned long long key = g_keys[p];

    float mask = 0.0f;
    float c0 = 0.0f, c1 = 0.0f, c2 = 0.0f;
    if (key != 0ull) {
        mask = 1.0f;
        int t = (int)(~(unsigned int)(key & 0xffffffffu));
        int i0 = triangles[t];
        int i1 = triangles[ntri + t];
        int i2 = triangles[2 * ntri + t];
        const float* C = colors + (size_t)b * 3 * nver;
        c0 = ((C[i0] + C[i1]) + C[i2]) / 3.0f;
        c1 = ((C[nver + i0] + C[nver + i1]) + C[nver + i2]) / 3.0f;
        c2 = ((C[2 * nver + i0] + C[2 * nver + i1]) + C[2 * nver + i2]) / 3.0f;
    }

    // Output layout: face_mask [B,1,H,W] then image [B,3,H,W], flattened.
    out[(size_t)b * HH * WW + pix] = mask;
    float* img = out + (size_t)B * HH * WW;
    img[((size_t)b * 3 + 0) * HH * WW + pix] = c0;
    img[((size_t)b * 3 + 1) * HH * WW + pix] = c1;
    img[((size_t)b * 3 + 2) * HH * WW + pix] = c2;
}

extern "C" void kernel_launch(void* const* d_in, const int* in_sizes, int n_in,
                              void* d_out, int out_size) {
    const float* vertices  = (const float*)d_in[0];
    const float* colors    = (const float*)d_in[1];
    const int*   triangles = (const int*)d_in[2];

    int ntri = in_sizes[2] / 3;
    int B    = out_size / (4 * HH * WW);
    int nver = in_sizes[0] / (3 * B);
    float* out = (float*)d_out;

    int npix = B * HH * WW;
    init_keys<<<(npix + 255) / 256, 256>>>(npix);

    int nwork = B * ntri;
    raster_kernel<<<(nwork + 127) / 128, 128>>>(vertices, triangles, B, ntri, nver);

    resolve_kernel<<<(npix + 255) / 256, 256>>>(colors, triangles, out, B, ntri, nver);
}